// round 1
// baseline (speedup 1.0000x reference)
#include <cuda_runtime.h>

#define NLEN   8192
#define NMODES 32
#define CH     64
#define BATCH  32
#define ROWS   (BATCH * CH)        // 2048
#define RN     256                 // residues r (threads per block)
#define QN     32                  // q = n / 256

// scratch (allocation-free rule: __device__ globals)
__device__ float g_X[ROWS * NMODES * 2];   // [row][m][re,im]  row = b*64 + i
__device__ float g_C[ROWS * NMODES * 2];   // [row][m][re,im]  row = b*64 + o

// cos(2*pi*k/32), k = 0..31 (compile-time constants -> FFMA immediates)
__device__ constexpr float COS32[32] = {
     1.0f,                  0.9807852804032304f,  0.9238795325112868f,  0.8314696123025452f,
     0.7071067811865476f,   0.5555702330196022f,  0.3826834323650898f,  0.1950903220161283f,
     0.0f,                 -0.1950903220161283f, -0.3826834323650898f, -0.5555702330196022f,
    -0.7071067811865476f,  -0.8314696123025452f, -0.9238795325112868f, -0.9807852804032304f,
    -1.0f,                 -0.9807852804032304f, -0.9238795325112868f, -0.8314696123025452f,
    -0.7071067811865476f,  -0.5555702330196022f, -0.3826834323650898f, -0.1950903220161283f,
     0.0f,                  0.1950903220161283f,  0.3826834323650898f,  0.5555702330196022f,
     0.7071067811865476f,   0.8314696123025452f,  0.9238795325112868f,  0.9807852804032304f
};
// sin(2*pi*k/32) = COS32[(k+24)&31]

static constexpr float TWO_PI_OVER_N = 6.283185307179586476925286766559e0f / 8192.0f;

// ---------------------------------------------------------------------------
// Kernel 1: forward truncated DFT.  One block per row (b,i), 256 threads = r.
// Thread t: stage1 = 32-point real DFT of x[256q + t] over q (constants),
// stage2 = rotate mode m by e^{-2pi i m t / 8192}, then block-reduce over t.
// ---------------------------------------------------------------------------
__global__ void __launch_bounds__(RN) fwd_dft_kernel(const float* __restrict__ x) {
    const int row = blockIdx.x;
    const int t   = threadIdx.x;
    const float* xr = x + (size_t)row * NLEN;

    float xq[QN];
#pragma unroll
    for (int q = 0; q < QN; q++) xq[q] = xr[q * RN + t];

    float Tre[NMODES], Tim[NMODES];
#pragma unroll
    for (int m = 0; m < NMODES; m++) { Tre[m] = 0.0f; Tim[m] = 0.0f; }

#pragma unroll
    for (int q = 0; q < QN; q++) {
#pragma unroll
        for (int m = 0; m < NMODES; m++) {
            const int k = (m * q) & 31;
            Tre[m] = fmaf(xq[q],  COS32[k],            Tre[m]);   // +cos
            Tim[m] = fmaf(xq[q], -COS32[(k + 24) & 31], Tim[m]);  // -sin
        }
    }

    // stage2 rotation base: e^{-2pi i t / 8192}
    float sb, cb;
    __sincosf(-(float)t * TWO_PI_OVER_N, &sb, &cb);
    float rre = 1.0f, rim = 0.0f;

    __shared__ float sred[8][2 * NMODES];
    const int wid = t >> 5, lane = t & 31;

#pragma unroll
    for (int m = 0; m < NMODES; m++) {
        float vr = Tre[m] * rre - Tim[m] * rim;
        float vi = Tre[m] * rim + Tim[m] * rre;
        // advance rotation
        float nr = rre * cb - rim * sb;
        float ni = rre * sb + rim * cb;
        rre = nr; rim = ni;
        // warp reduce
#pragma unroll
        for (int off = 16; off; off >>= 1) {
            vr += __shfl_xor_sync(0xFFFFFFFFu, vr, off);
            vi += __shfl_xor_sync(0xFFFFFFFFu, vi, off);
        }
        if (lane == 0) { sred[wid][2 * m] = vr; sred[wid][2 * m + 1] = vi; }
    }
    __syncthreads();

    if (t < 2 * NMODES) {
        float s = 0.0f;
#pragma unroll
        for (int w = 0; w < 8; w++) s += sred[w][t];
        g_X[row * (2 * NMODES) + t] = s;
    }
}

// ---------------------------------------------------------------------------
// Kernel 2: per-mode channel mix  Y[b,o,m] = sum_i X[b,i,m] * W[i,o,m],
// fused with irfft scaling a_m = (m==0 ? 1 : 2)/8192.
// Grid: (m, b); 64 threads = o.
// ---------------------------------------------------------------------------
__global__ void __launch_bounds__(CH) mix_kernel(const float* __restrict__ wr,
                                                 const float* __restrict__ wi) {
    const int m = blockIdx.x;
    const int b = blockIdx.y;
    const int o = threadIdx.x;

    __shared__ float xs[CH][2];
    {
        const int i = o;  // 64 threads load 64 channels
        xs[i][0] = g_X[((b * CH + i) * NMODES + m) * 2 + 0];
        xs[i][1] = g_X[((b * CH + i) * NMODES + m) * 2 + 1];
    }
    __syncthreads();

    float yre = 0.0f, yim = 0.0f;
#pragma unroll 4
    for (int i = 0; i < CH; i++) {
        const float wre = wr[(i * CH + o) * NMODES + m];
        const float wim = wi[(i * CH + o) * NMODES + m];
        const float xre = xs[i][0], xim = xs[i][1];
        yre = fmaf(xre, wre, yre);
        yre = fmaf(-xim, wim, yre);
        yim = fmaf(xre, wim, yim);
        yim = fmaf(xim, wre, yim);
    }
    const float a = (m == 0 ? 1.0f : 2.0f) / (float)NLEN;
    g_C[((b * CH + o) * NMODES + m) * 2 + 0] = yre * a;
    g_C[((b * CH + o) * NMODES + m) * 2 + 1] = yim * a;
}

// ---------------------------------------------------------------------------
// Kernel 3: inverse truncated DFT.  One block per row (b,o), 256 threads = r.
// Thread t: D[m] = C[m] * e^{+2pi i m t/8192}; out[256q+t] =
//   sum_m Dre[m]*cos(2pi mq/32) - Dim[m]*sin(2pi mq/32)   (constants again).
// ---------------------------------------------------------------------------
__global__ void __launch_bounds__(RN) inv_dft_kernel(float* __restrict__ out) {
    const int row = blockIdx.x;
    const int t   = threadIdx.x;

    __shared__ float cs[2 * NMODES];
    if (t < 2 * NMODES) cs[t] = g_C[row * (2 * NMODES) + t];
    __syncthreads();

    float sb, cb;
    __sincosf((float)t * TWO_PI_OVER_N, &sb, &cb);
    float rre = 1.0f, rim = 0.0f;

    float Dre[NMODES], Dim[NMODES];
#pragma unroll
    for (int m = 0; m < NMODES; m++) {
        const float cre = cs[2 * m], cim = cs[2 * m + 1];
        Dre[m] = cre * rre - cim * rim;
        Dim[m] = cre * rim + cim * rre;
        float nr = rre * cb - rim * sb;
        float ni = rre * sb + rim * cb;
        rre = nr; rim = ni;
    }

    float* orow = out + (size_t)row * NLEN;
#pragma unroll
    for (int q = 0; q < QN; q++) {
        float a0 = 0.0f, a1 = 0.0f, a2 = 0.0f, a3 = 0.0f;  // 4 chains for ILP
#pragma unroll
        for (int m = 0; m < NMODES; m += 4) {
            const int k0 = (m * q) & 31,       k1 = ((m + 1) * q) & 31;
            const int k2 = ((m + 2) * q) & 31, k3 = ((m + 3) * q) & 31;
            a0 = fmaf(Dre[m    ],  COS32[k0],            a0);
            a0 = fmaf(Dim[m    ], -COS32[(k0 + 24) & 31], a0);
            a1 = fmaf(Dre[m + 1],  COS32[k1],            a1);
            a1 = fmaf(Dim[m + 1], -COS32[(k1 + 24) & 31], a1);
            a2 = fmaf(Dre[m + 2],  COS32[k2],            a2);
            a2 = fmaf(Dim[m + 2], -COS32[(k2 + 24) & 31], a2);
            a3 = fmaf(Dre[m + 3],  COS32[k3],            a3);
            a3 = fmaf(Dim[m + 3], -COS32[(k3 + 24) & 31], a3);
        }
        orow[q * RN + t] = (a0 + a1) + (a2 + a3);
    }
}

// ---------------------------------------------------------------------------
extern "C" void kernel_launch(void* const* d_in, const int* in_sizes, int n_in,
                              void* d_out, int out_size) {
    const float* x  = (const float*)d_in[0];
    const float* wr = (const float*)d_in[1];
    const float* wi = (const float*)d_in[2];
    float* out = (float*)d_out;

    fwd_dft_kernel<<<ROWS, RN>>>(x);
    mix_kernel<<<dim3(NMODES, BATCH), CH>>>(wr, wi);
    inv_dft_kernel<<<ROWS, RN>>>(out);
}

// round 2
// speedup vs baseline: 1.4554x; 1.4554x over previous
#include <cuda_runtime.h>

#define NLEN   8192
#define NMODES 32
#define CH     64
#define BATCH  32
#define ROWS   (BATCH * CH)        // 2048
#define RN     256                 // residues t (threads per block)
#define QN     32                  // q = n / 256

// scratch (allocation-free rule: __device__ globals)
__device__ float g_X[ROWS * NMODES * 2];   // [row][m][re,im]  row = b*64 + i
__device__ float g_C[ROWS * NMODES * 2];   // [row][m][re,im]  row = b*64 + o

// cos(2*pi*k/32), k = 0..31 (compile-time constants -> FFMA immediates)
// sin(2*pi*k/32) = COS32[(k+24)&31]
__device__ constexpr float COS32[32] = {
     1.0f,                  0.9807852804032304f,  0.9238795325112868f,  0.8314696123025452f,
     0.7071067811865476f,   0.5555702330196022f,  0.3826834323650898f,  0.1950903220161283f,
     0.0f,                 -0.1950903220161283f, -0.3826834323650898f, -0.5555702330196022f,
    -0.7071067811865476f,  -0.8314696123025452f, -0.9238795325112868f, -0.9807852804032304f,
    -1.0f,                 -0.9807852804032304f, -0.9238795325112868f, -0.8314696123025452f,
    -0.7071067811865476f,  -0.5555702330196022f, -0.3826834323650898f, -0.1950903220161283f,
     0.0f,                  0.1950903220161283f,  0.3826834323650898f,  0.5555702330196022f,
     0.7071067811865476f,   0.8314696123025452f,  0.9238795325112868f,  0.9807852804032304f
};

static constexpr float TWO_PI_OVER_N = 6.283185307179586476925286766559e0f / 8192.0f;

// ---------------------------------------------------------------------------
// Kernel 1: forward truncated DFT with q<->32-q and m<->32-m folding.
// One block per row (b,i), 256 threads = residue t.
//   T[m] = sum_q x[256q+t] e^{-2pi i mq/32}      (folded: ~480 FMA)
//   A[m] = T[m] * e^{-2pi i m t/8192}            (recurrence)
//   block-reduce A over t via distributed butterfly + 8-warp shared combine.
// ---------------------------------------------------------------------------
__global__ void __launch_bounds__(RN) fwd_dft_kernel(const float* __restrict__ x) {
    const int row = blockIdx.x;
    const int t   = threadIdx.x;
    const float* xr = x + (size_t)row * NLEN;

    float xv[QN];
#pragma unroll
    for (int q = 0; q < QN; q++) xv[q] = xr[q * RN + t];

    const float x0 = xv[0], x16 = xv[16];
    float e[15], o[15];
#pragma unroll
    for (int q = 1; q <= 15; q++) {
        e[q - 1] = xv[q] + xv[32 - q];
        o[q - 1] = xv[q] - xv[32 - q];
    }

    // C[m] = sum_{q=1}^{15} e_q cos(2pi mq/32),  S[m] = sum o_q sin(2pi mq/32)
    float C[17], S[17];
    {
        float c0 = 0.0f, c16 = 0.0f;
#pragma unroll
        for (int q = 1; q <= 15; q++) {
            c0 += e[q - 1];
            c16 = (q & 1) ? (c16 - e[q - 1]) : (c16 + e[q - 1]);
        }
        C[0] = c0; S[0] = 0.0f; C[16] = c16; S[16] = 0.0f;
    }
#pragma unroll
    for (int m = 1; m <= 15; m++) {
        float c = 0.0f, s = 0.0f;
#pragma unroll
        for (int q = 1; q <= 15; q++) {
            const int k = (m * q) & 31;
            c = fmaf(e[q - 1], COS32[k], c);
            s = fmaf(o[q - 1], COS32[(k + 24) & 31], s);
        }
        C[m] = c; S[m] = s;
    }

    // rotation by e^{-2pi i m t/8192}, accumulate rotated components
    float sb, cb;
    __sincosf(-(float)t * TWO_PI_OVER_N, &sb, &cb);
    float rre = 1.0f, rim = 0.0f;
    const float xp = x0 + x16, xm = x0 - x16;

    float A[64];
#pragma unroll
    for (int m = 0; m < 32; m++) {
        float tre, tim;
        if (m <= 16) { tre = ((m & 1) ? xm : xp) + C[m];      tim = -S[m]; }
        else         { tre = ((m & 1) ? xm : xp) + C[32 - m]; tim =  S[32 - m]; }
        A[2 * m]     = tre * rre - tim * rim;
        A[2 * m + 1] = tre * rim + tim * rre;
        const float nr = rre * cb - rim * sb;
        const float ni = rre * sb + rim * cb;
        rre = nr; rim = ni;
    }

    // distributed butterfly reduce: 32 lanes x 64 values -> 2 values/lane
    const int lane = t & 31, wid = t >> 5;
#pragma unroll
    for (int s = 0; s < 5; s++) {
        const int half = 32 >> s;                 // 32,16,8,4,2
        const bool hi = (lane >> s) & 1;
#pragma unroll
        for (int i = 0; i < half; i++) {
            const float send  = hi ? A[i] : A[i + half];
            const float other = __shfl_xor_sync(0xFFFFFFFFu, send, 1 << s);
            A[i] = (hi ? A[i + half] : A[i]) + other;
        }
    }
    // lane holds components (comp, comp+1), comp = 2 * bitrev5(lane)
    const int comp = 2 * (int)(__brev((unsigned)lane) >> 27);

    __shared__ float sred[8][64];
    sred[wid][comp]     = A[0];
    sred[wid][comp + 1] = A[1];
    __syncthreads();

    if (t < 64) {
        float s = 0.0f;
#pragma unroll
        for (int w = 0; w < 8; w++) s += sred[w][t];
        g_X[row * 64 + t] = s;
    }
}

// ---------------------------------------------------------------------------
// Kernel 2: per-mode channel mix  Y[b,o,m] = sum_i X[b,i,m] * W[i,o,m],
// fused with irfft scaling a_m = (m==0 ? 1 : 2)/8192.
// ---------------------------------------------------------------------------
__global__ void __launch_bounds__(CH) mix_kernel(const float* __restrict__ wr,
                                                 const float* __restrict__ wi) {
    const int m = blockIdx.x;
    const int b = blockIdx.y;
    const int o = threadIdx.x;

    __shared__ float xs[CH][2];
    xs[o][0] = g_X[((b * CH + o) * NMODES + m) * 2 + 0];
    xs[o][1] = g_X[((b * CH + o) * NMODES + m) * 2 + 1];
    __syncthreads();

    float yre = 0.0f, yim = 0.0f;
#pragma unroll 4
    for (int i = 0; i < CH; i++) {
        const float wre = wr[(i * CH + o) * NMODES + m];
        const float wim = wi[(i * CH + o) * NMODES + m];
        const float xre = xs[i][0], xim = xs[i][1];
        yre = fmaf(xre, wre, yre);
        yre = fmaf(-xim, wim, yre);
        yim = fmaf(xre, wim, yim);
        yim = fmaf(xim, wre, yim);
    }
    const float a = (m == 0 ? 1.0f : 2.0f) / (float)NLEN;
    g_C[((b * CH + o) * NMODES + m) * 2 + 0] = yre * a;
    g_C[((b * CH + o) * NMODES + m) * 2 + 1] = yim * a;
}

// ---------------------------------------------------------------------------
// Kernel 3: inverse truncated DFT with m<->32-m and q<->32-q folding.
//   D[m] = C[m] * e^{+2pi i m t/8192}
//   E[q] = Dre[0] + (-1)^q Dre[16] + sum_{m=1}^{15} (Dre[m]+Dre[32-m]) cos(2pi mq/32)
//   O[q] =                            sum_{m=1}^{15} (Dim[m]-Dim[32-m]) sin(2pi mq/32)
//   out[256q+t] = E - O,  out[256(32-q)+t] = E + O
// ---------------------------------------------------------------------------
__global__ void __launch_bounds__(RN) inv_dft_kernel(float* __restrict__ out) {
    const int row = blockIdx.x;
    const int t   = threadIdx.x;

    __shared__ float cs[2 * NMODES];
    if (t < 2 * NMODES) cs[t] = g_C[row * (2 * NMODES) + t];
    __syncthreads();

    float sb, cb;
    __sincosf((float)t * TWO_PI_OVER_N, &sb, &cb);
    float rre = 1.0f, rim = 0.0f;

    float Dre[NMODES], Dim[NMODES];
#pragma unroll
    for (int m = 0; m < NMODES; m++) {
        const float cr = cs[2 * m], ci = cs[2 * m + 1];
        Dre[m] = cr * rre - ci * rim;
        Dim[m] = cr * rim + ci * rre;
        const float nr = rre * cb - rim * sb;
        const float ni = rre * sb + rim * cb;
        rre = nr; rim = ni;
    }

    float Are[15], Bim[15];
#pragma unroll
    for (int m = 1; m <= 15; m++) {
        Are[m - 1] = Dre[m] + Dre[32 - m];
        Bim[m - 1] = Dim[m] - Dim[32 - m];
    }
    const float d0 = Dre[0], d16 = Dre[16];

    float* orow = out + (size_t)row * NLEN + t;
#pragma unroll
    for (int q = 0; q <= 16; q++) {
        float Ea = 0.0f, Eb = 0.0f, Oa = 0.0f, Ob = 0.0f;
#pragma unroll
        for (int m = 1; m <= 15; m++) {
            const int k = (m * q) & 31;
            if (m & 1) {
                Ea = fmaf(Are[m - 1], COS32[k], Ea);
                Oa = fmaf(Bim[m - 1], COS32[(k + 24) & 31], Oa);
            } else {
                Eb = fmaf(Are[m - 1], COS32[k], Eb);
                Ob = fmaf(Bim[m - 1], COS32[(k + 24) & 31], Ob);
            }
        }
        const float E = ((q & 1) ? (d0 - d16) : (d0 + d16)) + (Ea + Eb);
        const float O = Oa + Ob;
        if (q == 0) {
            orow[0] = E;                    // O == 0 (all sin terms vanish)
        } else if (q == 16) {
            orow[16 * RN] = E;              // O == 0
        } else {
            orow[q * RN] = E - O;
            orow[(32 - q) * RN] = E + O;
        }
    }
}

// ---------------------------------------------------------------------------
extern "C" void kernel_launch(void* const* d_in, const int* in_sizes, int n_in,
                              void* d_out, int out_size) {
    const float* x  = (const float*)d_in[0];
    const float* wr = (const float*)d_in[1];
    const float* wi = (const float*)d_in[2];
    float* out = (float*)d_out;

    fwd_dft_kernel<<<ROWS, RN>>>(x);
    mix_kernel<<<dim3(NMODES, BATCH), CH>>>(wr, wi);
    inv_dft_kernel<<<ROWS, RN>>>(out);
}

// round 3
// speedup vs baseline: 2.4040x; 1.6518x over previous
#include <cuda_runtime.h>

#define NLEN   8192
#define NMODES 32
#define CH     64
#define BATCH  32
#define ROWS   (BATCH * CH)        // 2048
#define RN     256                 // residues t (threads per block)
#define QN     32                  // q = n / 256

// scratch (allocation-free rule: __device__ globals)
__device__ float2 g_X[ROWS * NMODES];   // [row][m] (re,im), row = b*64 + i

// cos(2*pi*k/32), k = 0..31 (compile-time constants -> FFMA immediates)
// sin(2*pi*k/32) = COS32[(k+24)&31]
__device__ constexpr float COS32[32] = {
     1.0f,                  0.9807852804032304f,  0.9238795325112868f,  0.8314696123025452f,
     0.7071067811865476f,   0.5555702330196022f,  0.3826834323650898f,  0.1950903220161283f,
     0.0f,                 -0.1950903220161283f, -0.3826834323650898f, -0.5555702330196022f,
    -0.7071067811865476f,  -0.8314696123025452f, -0.9238795325112868f, -0.9807852804032304f,
    -1.0f,                 -0.9807852804032304f, -0.9238795325112868f, -0.8314696123025452f,
    -0.7071067811865476f,  -0.5555702330196022f, -0.3826834323650898f, -0.1950903220161283f,
     0.0f,                  0.1950903220161283f,  0.3826834323650898f,  0.5555702330196022f,
     0.7071067811865476f,   0.8314696123025452f,  0.9238795325112868f,  0.9807852804032304f
};

static constexpr float TWO_PI_OVER_N = 6.283185307179586476925286766559e0f / 8192.0f;

// ---------------------------------------------------------------------------
// Kernel 1: forward truncated DFT (q<->32-q, m<->32-m folded).
// Split butterfly (2 x 32-wide) to cap live registers; forced 4 blocks/SM.
// ---------------------------------------------------------------------------
__global__ void __launch_bounds__(RN, 4) fwd_dft_kernel(const float* __restrict__ x) {
    const int row = blockIdx.x;
    const int t   = threadIdx.x;
    const float* xr = x + (size_t)row * NLEN;

    float xv[QN];
#pragma unroll
    for (int q = 0; q < QN; q++) xv[q] = xr[q * RN + t];

    const float x0 = xv[0], x16 = xv[16];
    float e[15], o[15];
#pragma unroll
    for (int q = 1; q <= 15; q++) {
        e[q - 1] = xv[q] + xv[32 - q];
        o[q - 1] = xv[q] - xv[32 - q];
    }

    float C[17], S[17];
    {
        float c0 = 0.0f, c16 = 0.0f;
#pragma unroll
        for (int q = 1; q <= 15; q++) {
            c0 += e[q - 1];
            c16 = (q & 1) ? (c16 - e[q - 1]) : (c16 + e[q - 1]);
        }
        C[0] = c0; S[0] = 0.0f; C[16] = c16; S[16] = 0.0f;
    }
#pragma unroll
    for (int m = 1; m <= 15; m++) {
        float c = 0.0f, s = 0.0f;
#pragma unroll
        for (int q = 1; q <= 15; q++) {
            const int k = (m * q) & 31;
            c = fmaf(e[q - 1], COS32[k], c);
            s = fmaf(o[q - 1], COS32[(k + 24) & 31], s);
        }
        C[m] = c; S[m] = s;
    }

    float sb, cb;
    __sincosf(-(float)t * TWO_PI_OVER_N, &sb, &cb);
    float rre = 1.0f, rim = 0.0f;
    const float xp = x0 + x16, xm = x0 - x16;

    const int lane = t & 31, wid = t >> 5;
    const int comp = (int)(__brev((unsigned)lane) >> 27);   // bitrev5(lane)
    __shared__ float sred[8][64];

    // ---- half 1: modes 0..15 ----
    {
        float A[32];
#pragma unroll
        for (int m = 0; m < 16; m++) {
            const float tre = ((m & 1) ? xm : xp) + C[m];
            const float tim = -S[m];
            A[2 * m]     = tre * rre - tim * rim;
            A[2 * m + 1] = tre * rim + tim * rre;
            const float nr = rre * cb - rim * sb;
            const float ni = rre * sb + rim * cb;
            rre = nr; rim = ni;
        }
#pragma unroll
        for (int s = 0; s < 5; s++) {
            const int half = 16 >> s;                 // 16,8,4,2,1
            const bool hi = (lane >> s) & 1;
#pragma unroll
            for (int i = 0; i < half; i++) {
                const float send  = hi ? A[i] : A[i + half];
                const float other = __shfl_xor_sync(0xFFFFFFFFu, send, 1 << s);
                A[i] = (hi ? A[i + half] : A[i]) + other;
            }
        }
        sred[wid][comp] = A[0];
    }
    // ---- half 2: modes 16..31 ----
    {
        float A[32];
#pragma unroll
        for (int m = 16; m < 32; m++) {
            const float tre = ((m & 1) ? xm : xp) + C[32 - m];
            const float tim = S[32 - m];
            A[2 * (m - 16)]     = tre * rre - tim * rim;
            A[2 * (m - 16) + 1] = tre * rim + tim * rre;
            const float nr = rre * cb - rim * sb;
            const float ni = rre * sb + rim * cb;
            rre = nr; rim = ni;
        }
#pragma unroll
        for (int s = 0; s < 5; s++) {
            const int half = 16 >> s;
            const bool hi = (lane >> s) & 1;
#pragma unroll
            for (int i = 0; i < half; i++) {
                const float send  = hi ? A[i] : A[i + half];
                const float other = __shfl_xor_sync(0xFFFFFFFFu, send, 1 << s);
                A[i] = (hi ? A[i + half] : A[i]) + other;
            }
        }
        sred[wid][32 + comp] = A[0];
    }
    __syncthreads();

    if (t < 32) {
        float sre = 0.0f, sim = 0.0f;
#pragma unroll
        for (int w = 0; w < 8; w++) {
            sre += sred[w][2 * t];
            sim += sred[w][2 * t + 1];
        }
        g_X[row * NMODES + t] = make_float2(sre, sim);
    }
}

// ---------------------------------------------------------------------------
// Kernel 2: fused channel-mix + inverse truncated DFT.
// Block = row (b,o).  Phase A: C[m] = sum_i X[b,i,m] * W[i,o,m] (scaled by
// a_m = (m==0?1:2)/8192), reduced over 8 i-chunks via smem.
// Phase B: rotation + folded synthesis (as before), reading cs[] from smem.
// ---------------------------------------------------------------------------
__global__ void __launch_bounds__(RN) inv_mix_kernel(const float* __restrict__ wr,
                                                     const float* __restrict__ wi,
                                                     float* __restrict__ out) {
    const int row = blockIdx.x;
    const int b = row >> 6;
    const int o = row & 63;
    const int t = threadIdx.x;

    __shared__ float red[8][64];
    __shared__ float cs[64];

    // ---- Phase A: channel mix ----
    {
        const int m     = t & 31;
        const int chunk = t >> 5;   // == warp id
        float yre = 0.0f, yim = 0.0f;
#pragma unroll
        for (int j = 0; j < 8; j++) {
            const int i = chunk * 8 + j;
            const float2 xv = g_X[(b * CH + i) * NMODES + m];
            const float wre = wr[(i * CH + o) * NMODES + m];
            const float wim = wi[(i * CH + o) * NMODES + m];
            yre = fmaf(xv.x, wre, yre);
            yre = fmaf(-xv.y, wim, yre);
            yim = fmaf(xv.x, wim, yim);
            yim = fmaf(xv.y, wre, yim);
        }
        red[chunk][2 * m]     = yre;
        red[chunk][2 * m + 1] = yim;
    }
    __syncthreads();
    if (t < 64) {
        float s = 0.0f;
#pragma unroll
        for (int w = 0; w < 8; w++) s += red[w][t];
        const int m = t >> 1;
        const float a = (m == 0 ? 1.0f : 2.0f) / (float)NLEN;
        cs[t] = s * a;
    }
    __syncthreads();

    // ---- Phase B: inverse DFT ----
    float sb, cb;
    __sincosf((float)t * TWO_PI_OVER_N, &sb, &cb);
    float rre = 1.0f, rim = 0.0f;

    float Dre[NMODES], Dim[NMODES];
#pragma unroll
    for (int m = 0; m < NMODES; m++) {
        const float cr = cs[2 * m], ci = cs[2 * m + 1];
        Dre[m] = cr * rre - ci * rim;
        Dim[m] = cr * rim + ci * rre;
        const float nr = rre * cb - rim * sb;
        const float ni = rre * sb + rim * cb;
        rre = nr; rim = ni;
    }

    float Are[15], Bim[15];
#pragma unroll
    for (int m = 1; m <= 15; m++) {
        Are[m - 1] = Dre[m] + Dre[32 - m];
        Bim[m - 1] = Dim[m] - Dim[32 - m];
    }
    const float d0 = Dre[0], d16 = Dre[16];

    float* orow = out + (size_t)row * NLEN + t;
#pragma unroll
    for (int q = 0; q <= 16; q++) {
        float Ea = 0.0f, Eb = 0.0f, Oa = 0.0f, Ob = 0.0f;
#pragma unroll
        for (int m = 1; m <= 15; m++) {
            const int k = (m * q) & 31;
            if (m & 1) {
                Ea = fmaf(Are[m - 1], COS32[k], Ea);
                Oa = fmaf(Bim[m - 1], COS32[(k + 24) & 31], Oa);
            } else {
                Eb = fmaf(Are[m - 1], COS32[k], Eb);
                Ob = fmaf(Bim[m - 1], COS32[(k + 24) & 31], Ob);
            }
        }
        const float E = ((q & 1) ? (d0 - d16) : (d0 + d16)) + (Ea + Eb);
        const float O = Oa + Ob;
        if (q == 0) {
            orow[0] = E;                    // sin terms vanish
        } else if (q == 16) {
            orow[16 * RN] = E;
        } else {
            orow[q * RN] = E - O;
            orow[(32 - q) * RN] = E + O;
        }
    }
}

// ---------------------------------------------------------------------------
extern "C" void kernel_launch(void* const* d_in, const int* in_sizes, int n_in,
                              void* d_out, int out_size) {
    const float* x  = (const float*)d_in[0];
    const float* wr = (const float*)d_in[1];
    const float* wi = (const float*)d_in[2];
    float* out = (float*)d_out;

    fwd_dft_kernel<<<ROWS, RN>>>(x);
    inv_mix_kernel<<<ROWS, RN>>>(wr, wi, out);
}

// round 4
// speedup vs baseline: 2.6291x; 1.0936x over previous
#include <cuda_runtime.h>

#define NLEN   8192
#define NMODES 32
#define CH     64
#define BATCH  32
#define ROWS   (BATCH * CH)        // 2048
#define RN     256                 // residues t (threads per block)
#define QN     32                  // q = n / 256

// scratch (allocation-free rule: __device__ globals)
__device__ float2 g_X[ROWS * NMODES];   // [row][m] (re,im), row = b*64 + i

// cos(2*pi*k/32), k = 0..31 (compile-time constants -> FFMA immediates)
// sin(2*pi*k/32) = COS32[(k+24)&31]
__device__ constexpr float COS32[32] = {
     1.0f,                  0.9807852804032304f,  0.9238795325112868f,  0.8314696123025452f,
     0.7071067811865476f,   0.5555702330196022f,  0.3826834323650898f,  0.1950903220161283f,
     0.0f,                 -0.1950903220161283f, -0.3826834323650898f, -0.5555702330196022f,
    -0.7071067811865476f,  -0.8314696123025452f, -0.9238795325112868f, -0.9807852804032304f,
    -1.0f,                 -0.9807852804032304f, -0.9238795325112868f, -0.8314696123025452f,
    -0.7071067811865476f,  -0.5555702330196022f, -0.3826834323650898f, -0.1950903220161283f,
     0.0f,                  0.1950903220161283f,  0.3826834323650898f,  0.5555702330196022f,
     0.7071067811865476f,   0.8314696123025452f,  0.9238795325112868f,  0.9807852804032304f
};

static constexpr float TWO_PI_OVER_N   = 6.283185307179586476925286766559e0f / 8192.0f;
static constexpr float TWO_PI_OVER_256 = 6.283185307179586476925286766559e0f / 256.0f;

// ---------------------------------------------------------------------------
// Kernel 1: forward truncated DFT.
// Stage 1 uses q<->32-q AND m<->16-m folding (~260 FMA), then rotation by
// e^{-2pi i m t/8192} and a 2x32-wide distributed butterfly reduction.
// ---------------------------------------------------------------------------
__global__ void __launch_bounds__(RN, 4) fwd_dft_kernel(const float* __restrict__ x) {
    const int row = blockIdx.x;
    const int t   = threadIdx.x;
    const float* xr = x + (size_t)row * NLEN;

    float xv[QN];
#pragma unroll
    for (int q = 0; q < QN; q++) xv[q] = xr[q * RN + t];

    const float x0 = xv[0], x16 = xv[16];
    float e[15], o[15];
#pragma unroll
    for (int q = 1; q <= 15; q++) {
        e[q - 1] = xv[q] + xv[32 - q];
        o[q - 1] = xv[q] - xv[32 - q];
    }

    float C[17], S[17];
    {
        float c0 = 0.0f, c16 = 0.0f;
#pragma unroll
        for (int q = 1; q <= 15; q++) {
            c0 += e[q - 1];
            c16 = (q & 1) ? (c16 - e[q - 1]) : (c16 + e[q - 1]);
        }
        C[0] = c0; S[0] = 0.0f; C[16] = c16; S[16] = 0.0f;
    }
    // m = 1..7 with m<->16-m fold via q-parity split
#pragma unroll
    for (int m = 1; m <= 7; m++) {
        float ce = 0.0f, co = 0.0f, se = 0.0f, so = 0.0f;
#pragma unroll
        for (int q = 1; q <= 15; q++) {
            const int k = (m * q) & 31;
            const float cc = COS32[k];
            const float ss = COS32[(k + 24) & 31];
            if (q & 1) { co = fmaf(e[q - 1], cc, co); so = fmaf(o[q - 1], ss, so); }
            else       { ce = fmaf(e[q - 1], cc, ce); se = fmaf(o[q - 1], ss, se); }
        }
        C[m] = ce + co;  C[16 - m] = ce - co;
        S[m] = se + so;  S[16 - m] = so - se;
    }
    // m = 8: cos(pi q/2), sin(pi q/2) patterns -> pure adds
    C[8] = ((-e[1] + e[3]) + (-e[5] + e[7])) + ((-e[9] + e[11]) - e[13]);
    S[8] = ((o[0] - o[2]) + (o[4] - o[6])) + ((o[8] - o[10]) + (o[12] - o[14]));

    float sb, cb;
    __sincosf(-(float)t * TWO_PI_OVER_N, &sb, &cb);
    float rre = 1.0f, rim = 0.0f;
    const float xp = x0 + x16, xm = x0 - x16;

    const int lane = t & 31, wid = t >> 5;
    const int comp = (int)(__brev((unsigned)lane) >> 27);   // bitrev5(lane)
    __shared__ float sred[8][64];

    // ---- half 1: modes 0..15 ----
    {
        float A[32];
#pragma unroll
        for (int m = 0; m < 16; m++) {
            const float tre = ((m & 1) ? xm : xp) + C[m];
            const float tim = -S[m];
            A[2 * m]     = tre * rre - tim * rim;
            A[2 * m + 1] = tre * rim + tim * rre;
            const float nr = rre * cb - rim * sb;
            const float ni = rre * sb + rim * cb;
            rre = nr; rim = ni;
        }
#pragma unroll
        for (int s = 0; s < 5; s++) {
            const int half = 16 >> s;                 // 16,8,4,2,1
            const bool hi = (lane >> s) & 1;
#pragma unroll
            for (int i = 0; i < half; i++) {
                const float send  = hi ? A[i] : A[i + half];
                const float other = __shfl_xor_sync(0xFFFFFFFFu, send, 1 << s);
                A[i] = (hi ? A[i + half] : A[i]) + other;
            }
        }
        sred[wid][comp] = A[0];
    }
    // ---- half 2: modes 16..31 ----
    {
        float A[32];
#pragma unroll
        for (int m = 16; m < 32; m++) {
            const float tre = ((m & 1) ? xm : xp) + C[32 - m];
            const float tim = S[32 - m];
            A[2 * (m - 16)]     = tre * rre - tim * rim;
            A[2 * (m - 16) + 1] = tre * rim + tim * rre;
            const float nr = rre * cb - rim * sb;
            const float ni = rre * sb + rim * cb;
            rre = nr; rim = ni;
        }
#pragma unroll
        for (int s = 0; s < 5; s++) {
            const int half = 16 >> s;
            const bool hi = (lane >> s) & 1;
#pragma unroll
            for (int i = 0; i < half; i++) {
                const float send  = hi ? A[i] : A[i + half];
                const float other = __shfl_xor_sync(0xFFFFFFFFu, send, 1 << s);
                A[i] = (hi ? A[i + half] : A[i]) + other;
            }
        }
        sred[wid][32 + comp] = A[0];
    }
    __syncthreads();

    if (t < 32) {
        float sre = 0.0f, sim = 0.0f;
#pragma unroll
        for (int w = 0; w < 8; w++) {
            sre += sred[w][2 * t];
            sim += sred[w][2 * t + 1];
        }
        g_X[row * NMODES + t] = make_float2(sre, sim);
    }
}

// ---------------------------------------------------------------------------
// Kernel 2: fused channel-mix + inverse truncated DFT.
// Phase A: C[m] = sum_i X[b,i,m] * W[i,o,m], scaled by (m==0?1:2)/8192.
// Phase B: single 16-step rotation chain (using rho^{32-m} = rho32*conj(rho^m))
// producing Are/Bim directly, then 4-way-folded synthesis (q, 16-q, 16+q, 32-q).
// ---------------------------------------------------------------------------
__global__ void __launch_bounds__(RN, 4) inv_mix_kernel(const float* __restrict__ wr,
                                                        const float* __restrict__ wi,
                                                        float* __restrict__ out) {
    const int row = blockIdx.x;
    const int b = row >> 6;
    const int o = row & 63;
    const int t = threadIdx.x;

    __shared__ float red[8][64];
    __shared__ float cs[64];

    // ---- Phase A: channel mix ----
    {
        const int m     = t & 31;
        const int chunk = t >> 5;   // == warp id
        float yre = 0.0f, yim = 0.0f;
#pragma unroll
        for (int j = 0; j < 8; j++) {
            const int i = chunk * 8 + j;
            const float2 xv = g_X[(b * CH + i) * NMODES + m];
            const float wre = wr[(i * CH + o) * NMODES + m];
            const float wim = wi[(i * CH + o) * NMODES + m];
            yre = fmaf(xv.x, wre, yre);
            yre = fmaf(-xv.y, wim, yre);
            yim = fmaf(xv.x, wim, yim);
            yim = fmaf(xv.y, wre, yim);
        }
        red[chunk][2 * m]     = yre;
        red[chunk][2 * m + 1] = yim;
    }
    __syncthreads();
    if (t < 64) {
        float s = 0.0f;
#pragma unroll
        for (int w = 0; w < 8; w++) s += red[w][t];
        const int m = t >> 1;
        const float a = (m == 0 ? 1.0f : 2.0f) / (float)NLEN;
        cs[t] = s * a;
    }
    __syncthreads();

    // ---- Phase B: inverse DFT ----
    float sb, cb, s32, c32;
    __sincosf((float)t * TWO_PI_OVER_N, &sb, &cb);     // rho   = e^{+2pi i t/8192}
    __sincosf((float)t * TWO_PI_OVER_256, &s32, &c32); // rho32 = rho^32

    const float d0 = cs[0];
    float rre = 1.0f, rim = 0.0f;

    float Are[15], Bim[15];
#pragma unroll
    for (int m = 1; m <= 15; m++) {
        const float nr = rre * cb - rim * sb;           // advance chain -> rho^m
        const float ni = rre * sb + rim * cb;
        rre = nr; rim = ni;
        const float ar = cs[2 * m],        ai = cs[2 * m + 1];
        const float br = cs[2 * (32 - m)], bi = cs[2 * (32 - m) + 1];
        // u = rho32 * conj(rho^m)
        const float ur = c32 * rre + s32 * rim;
        const float ui = s32 * rre - c32 * rim;
        // Are = Re(D[m]) + Re(D[32-m]);  Bim = Im(D[m]) - Im(D[32-m])
        Are[m - 1] = (ar * rre - ai * rim) + (br * ur - bi * ui);
        Bim[m - 1] = (ar * rim + ai * rre) - (br * ui + bi * ur);
    }
    float d16;
    {
        const float nr = rre * cb - rim * sb;           // -> rho^16
        const float ni = rre * sb + rim * cb;
        d16 = cs[32] * nr - cs[33] * ni;
    }

    float* orow = out + (size_t)row * NLEN + t;
#pragma unroll
    for (int q = 0; q <= 8; q++) {
        float Ea = 0.0f, Eb = 0.0f, Oa = 0.0f, Ob = 0.0f;
#pragma unroll
        for (int m = 1; m <= 15; m++) {
            const int k = (m * q) & 31;
            const float cc = COS32[k];
            const float ss = COS32[(k + 24) & 31];
            if (m & 1) { Ea = fmaf(Are[m - 1], cc, Ea); Oa = fmaf(Bim[m - 1], ss, Oa); }
            else       { Eb = fmaf(Are[m - 1], cc, Eb); Ob = fmaf(Bim[m - 1], ss, Ob); }
        }
        const float base = (q & 1) ? (d0 - d16) : (d0 + d16);
        const float E1 = base + Ea + Eb;   // E(q)
        const float O1 = Oa + Ob;          // O(q)
        const float E2 = base + Eb - Ea;   // E(16-q)
        const float O2 = Oa - Ob;          // O(16-q)
        if (q == 0) {
            orow[0]       = E1;            // O(0)  == 0
            orow[16 * RN] = E2;            // O(16) == 0
        } else if (q == 8) {
            orow[8 * RN]  = E1 - O1;
            orow[24 * RN] = E1 + O1;
        } else {
            orow[q * RN]        = E1 - O1;
            orow[(32 - q) * RN] = E1 + O1;
            orow[(16 - q) * RN] = E2 - O2;
            orow[(16 + q) * RN] = E2 + O2;
        }
    }
}

// ---------------------------------------------------------------------------
extern "C" void kernel_launch(void* const* d_in, const int* in_sizes, int n_in,
                              void* d_out, int out_size) {
    const float* x  = (const float*)d_in[0];
    const float* wr = (const float*)d_in[1];
    const float* wi = (const float*)d_in[2];
    float* out = (float*)d_out;

    fwd_dft_kernel<<<ROWS, RN>>>(x);
    inv_mix_kernel<<<ROWS, RN>>>(wr, wi, out);
}

// round 5
// speedup vs baseline: 2.6309x; 1.0007x over previous
#include <cuda_runtime.h>

#define NLEN   8192
#define NMODES 32
#define CH     64
#define BATCH  32
#define ROWS   (BATCH * CH)        // 2048
#define RN     256                 // residues t (threads per block)
#define QN     32                  // q = n / 256

// scratch (allocation-free rule: __device__ globals)
__device__ float2 g_X[ROWS * NMODES];   // [row][m] (re,im), row = b*64 + i

// cos(2*pi*k/32), k = 0..31 (compile-time constants -> FFMA immediates)
// sin(2*pi*k/32) = COS32[(k+24)&31]
__device__ constexpr float COS32[32] = {
     1.0f,                  0.9807852804032304f,  0.9238795325112868f,  0.8314696123025452f,
     0.7071067811865476f,   0.5555702330196022f,  0.3826834323650898f,  0.1950903220161283f,
     0.0f,                 -0.1950903220161283f, -0.3826834323650898f, -0.5555702330196022f,
    -0.7071067811865476f,  -0.8314696123025452f, -0.9238795325112868f, -0.9807852804032304f,
    -1.0f,                 -0.9807852804032304f, -0.9238795325112868f, -0.8314696123025452f,
    -0.7071067811865476f,  -0.5555702330196022f, -0.3826834323650898f, -0.1950903220161283f,
     0.0f,                  0.1950903220161283f,  0.3826834323650898f,  0.5555702330196022f,
     0.7071067811865476f,   0.8314696123025452f,  0.9238795325112868f,  0.9807852804032304f
};

static constexpr float TWO_PI_OVER_N   = 6.283185307179586476925286766559e0f / 8192.0f;
static constexpr float TWO_PI_OVER_256 = 6.283185307179586476925286766559e0f / 256.0f;

// ---------------------------------------------------------------------------
// Kernel 1: forward truncated DFT.
// Streamed stage-1 (paired loads, parity-split C/S accumulators), then
// rotation by e^{-2pi i m t/8192} in 4 independent chains of 8 modes, each
// followed by a 16-value distributed butterfly reduction.
// ---------------------------------------------------------------------------
__global__ void __launch_bounds__(RN, 4) fwd_dft_kernel(const float* __restrict__ x) {
    const int row = blockIdx.x;
    const int t   = threadIdx.x;
    const float* xr = x + (size_t)row * NLEN;

    const float x0  = xr[t];
    const float x16 = xr[16 * RN + t];

    float c0 = 0.0f, c16 = 0.0f, C8 = 0.0f, S8 = 0.0f;
    float ce[7], co[7], se[7], so[7];
#pragma unroll
    for (int m = 0; m < 7; m++) { ce[m] = co[m] = se[m] = so[m] = 0.0f; }

#pragma unroll
    for (int q = 1; q <= 15; q++) {
        const float a  = xr[q * RN + t];
        const float bq = xr[(32 - q) * RN + t];
        const float e = a + bq, o = a - bq;
        c0 += e;
        c16 = (q & 1) ? (c16 - e) : (c16 + e);
        if (q & 1) { S8 = (q & 2) ? (S8 - o) : (S8 + o); }
        else       { C8 = (q & 2) ? (C8 - e) : (C8 + e); }
#pragma unroll
        for (int m = 1; m <= 7; m++) {
            const int k = (m * q) & 31;
            const float cc = COS32[k];
            const float ss = COS32[(k + 24) & 31];
            if (q & 1) { co[m - 1] = fmaf(e, cc, co[m - 1]); so[m - 1] = fmaf(o, ss, so[m - 1]); }
            else       { ce[m - 1] = fmaf(e, cc, ce[m - 1]); se[m - 1] = fmaf(o, ss, se[m - 1]); }
        }
    }

    float C[17], S[17];
    C[0] = c0;  S[0] = 0.0f;
    C[16] = c16; S[16] = 0.0f;
    C[8] = C8;  S[8] = S8;
#pragma unroll
    for (int m = 1; m <= 7; m++) {
        C[m] = ce[m - 1] + co[m - 1];  C[16 - m] = ce[m - 1] - co[m - 1];
        S[m] = se[m - 1] + so[m - 1];  S[16 - m] = so[m - 1] - se[m - 1];
    }

    // rho = e^{-2pi i t/8192}; powers for 4 chain starts
    float s1, c1;
    __sincosf(-(float)t * TWO_PI_OVER_N, &s1, &c1);
    const float c2 = c1 * c1 - s1 * s1, s2 = 2.0f * c1 * s1;        // rho^2
    const float c4 = c2 * c2 - s2 * s2, s4 = 2.0f * c2 * s2;        // rho^4
    const float c8 = c4 * c4 - s4 * s4, s8 = 2.0f * c4 * s4;        // rho^8
    const float c16r = c8 * c8 - s8 * s8, s16r = 2.0f * c8 * s8;    // rho^16
    const float c24 = c16r * c8 - s16r * s8, s24 = c16r * s8 + s16r * c8; // rho^24

    const float xp = x0 + x16, xm = x0 - x16;
    const int lane = t & 31, wid = t >> 5;
    const int comp16 = (int)(__brev((unsigned)(lane & 15)) >> 28);
    __shared__ float sred[8][64];

#pragma unroll
    for (int g = 0; g < 4; g++) {
        float rre, rim;
        if      (g == 0) { rre = 1.0f;  rim = 0.0f;  }
        else if (g == 1) { rre = c8;    rim = s8;    }
        else if (g == 2) { rre = c16r;  rim = s16r;  }
        else             { rre = c24;   rim = s24;   }

        float A[16];
#pragma unroll
        for (int j = 0; j < 8; j++) {
            const int m = 8 * g + j;
            float tre, tim;
            if (m <= 16) { tre = ((m & 1) ? xm : xp) + C[m];      tim = -S[m]; }
            else         { tre = ((m & 1) ? xm : xp) + C[32 - m]; tim =  S[32 - m]; }
            A[2 * j]     = tre * rre - tim * rim;
            A[2 * j + 1] = tre * rim + tim * rre;
            const float nr = rre * c1 - rim * s1;
            const float ni = rre * s1 + rim * c1;
            rre = nr; rim = ni;
        }
        // 16-value butterfly over 32 lanes
#pragma unroll
        for (int s = 0; s < 4; s++) {
            const int half = 8 >> s;                 // 8,4,2,1
            const bool hi = (lane >> s) & 1;
#pragma unroll
            for (int i = 0; i < half; i++) {
                const float send  = hi ? A[i] : A[i + half];
                const float other = __shfl_xor_sync(0xFFFFFFFFu, send, 1 << s);
                A[i] = (hi ? A[i + half] : A[i]) + other;
            }
        }
        A[0] += __shfl_xor_sync(0xFFFFFFFFu, A[0], 16);
        if (lane < 16) sred[wid][g * 16 + comp16] = A[0];
    }
    __syncthreads();

    if (t < 64) {
        float s = 0.0f;
#pragma unroll
        for (int w = 0; w < 8; w++) s += sred[w][t];
        ((float*)g_X)[row * 64 + t] = s;   // interleaved (re,im) matches float2
    }
}

// ---------------------------------------------------------------------------
// Kernel 2: fused channel-mix + inverse truncated DFT.
// Phase A: C[m] = sum_i X[b,i,m] * W[i,o,m], scaled by (m==0?1:2)/8192.
// Phase B: 4 independent depth-4 rotation chains produce Are/Bim directly
// (rho^{32-m} = rho32*conj(rho^m)); 4-way-folded synthesis (q,16-q,16+q,32-q).
// ---------------------------------------------------------------------------
__global__ void __launch_bounds__(RN, 4) inv_mix_kernel(const float* __restrict__ wr,
                                                        const float* __restrict__ wi,
                                                        float* __restrict__ out) {
    const int row = blockIdx.x;
    const int b = row >> 6;
    const int o = row & 63;
    const int t = threadIdx.x;

    __shared__ float red[8][64];
    __shared__ float cs[64];

    // ---- Phase A: channel mix ----
    {
        const int m     = t & 31;
        const int chunk = t >> 5;   // == warp id
        float yre = 0.0f, yim = 0.0f;
#pragma unroll
        for (int j = 0; j < 8; j++) {
            const int i = chunk * 8 + j;
            const float2 xv = g_X[(b * CH + i) * NMODES + m];
            const float wre = wr[(i * CH + o) * NMODES + m];
            const float wim = wi[(i * CH + o) * NMODES + m];
            yre = fmaf(xv.x, wre, yre);
            yre = fmaf(-xv.y, wim, yre);
            yim = fmaf(xv.x, wim, yim);
            yim = fmaf(xv.y, wre, yim);
        }
        red[chunk][2 * m]     = yre;
        red[chunk][2 * m + 1] = yim;
    }
    __syncthreads();
    if (t < 64) {
        float s = 0.0f;
#pragma unroll
        for (int w = 0; w < 8; w++) s += red[w][t];
        const int m = t >> 1;
        const float a = (m == 0 ? 1.0f : 2.0f) / (float)NLEN;
        cs[t] = s * a;
    }
    __syncthreads();

    // ---- Phase B: inverse DFT ----
    float s1, c1, s32, c32;
    __sincosf((float)t * TWO_PI_OVER_N, &s1, &c1);     // rho   = e^{+2pi i t/8192}
    __sincosf((float)t * TWO_PI_OVER_256, &s32, &c32); // rho32 = rho^32
    const float c2 = c1 * c1 - s1 * s1, s2 = 2.0f * c1 * s1;   // rho^2
    const float c3 = c2 * c1 - s2 * s1, s3 = c2 * s1 + s2 * c1; // rho^3
    const float c4 = c2 * c2 - s2 * s2, s4 = 2.0f * c2 * s2;   // rho^4

    const float d0 = cs[0];
    float d16 = 0.0f;
    float Are[15], Bim[15];

#pragma unroll
    for (int g = 0; g < 4; g++) {
        float rre, rim;
        if      (g == 0) { rre = c1; rim = s1; }
        else if (g == 1) { rre = c2; rim = s2; }
        else if (g == 2) { rre = c3; rim = s3; }
        else             { rre = c4; rim = s4; }
        const int nsteps = (g == 3) ? 3 : 4;       // m0=4 -> m = 4,8,12
#pragma unroll
        for (int jj = 0; jj < 4; jj++) {
            if (jj < nsteps) {
                const int m = (g + 1) + 4 * jj;
                const float ar = cs[2 * m],        ai = cs[2 * m + 1];
                const float br = cs[2 * (32 - m)], bi = cs[2 * (32 - m) + 1];
                const float ur = c32 * rre + s32 * rim;     // rho32*conj(rho^m)
                const float ui = s32 * rre - c32 * rim;
                Are[m - 1] = (ar * rre - ai * rim) + (br * ur - bi * ui);
                Bim[m - 1] = (ar * rim + ai * rre) - (br * ui + bi * ur);
                const float nr = rre * c4 - rim * s4;       // advance by rho^4
                const float ni = rre * s4 + rim * c4;
                rre = nr; rim = ni;
            }
        }
        if (g == 3) d16 = cs[32] * rre - cs[33] * rim;      // chain ended at rho^16
    }

    float* orow = out + (size_t)row * NLEN + t;
#pragma unroll
    for (int q = 0; q <= 8; q++) {
        float Ea = 0.0f, Eb = 0.0f, Oa = 0.0f, Ob = 0.0f;
#pragma unroll
        for (int m = 1; m <= 15; m++) {
            const int k = (m * q) & 31;
            const float cc = COS32[k];
            const float ss = COS32[(k + 24) & 31];
            if (m & 1) { Ea = fmaf(Are[m - 1], cc, Ea); Oa = fmaf(Bim[m - 1], ss, Oa); }
            else       { Eb = fmaf(Are[m - 1], cc, Eb); Ob = fmaf(Bim[m - 1], ss, Ob); }
        }
        const float base = (q & 1) ? (d0 - d16) : (d0 + d16);
        const float E1 = base + Ea + Eb;   // E(q)
        const float O1 = Oa + Ob;          // O(q)
        const float E2 = base + Eb - Ea;   // E(16-q)
        const float O2 = Oa - Ob;          // O(16-q)
        if (q == 0) {
            orow[0]       = E1;            // O(0)  == 0
            orow[16 * RN] = E2;            // O(16) == 0
        } else if (q == 8) {
            orow[8 * RN]  = E1 - O1;
            orow[24 * RN] = E1 + O1;
        } else {
            orow[q * RN]        = E1 - O1;
            orow[(32 - q) * RN] = E1 + O1;
            orow[(16 - q) * RN] = E2 - O2;
            orow[(16 + q) * RN] = E2 + O2;
        }
    }
}

// ---------------------------------------------------------------------------
extern "C" void kernel_launch(void* const* d_in, const int* in_sizes, int n_in,
                              void* d_out, int out_size) {
    const float* x  = (const float*)d_in[0];
    const float* wr = (const float*)d_in[1];
    const float* wi = (const float*)d_in[2];
    float* out = (float*)d_out;

    fwd_dft_kernel<<<ROWS, RN>>>(x);
    inv_mix_kernel<<<ROWS, RN>>>(wr, wi, out);
}